// round 13
// baseline (speedup 1.0000x reference)
#include <cuda_runtime.h>
#include <cuda_bf16.h>

#define N_NODES 1000000

// 4 MB scratch for per-node exp-sums (static __device__ per allocation rules)
__device__ float g_rowsum[N_NODES];

__device__ __forceinline__ void pdl_trigger() {
    asm volatile("griddepcontrol.launch_dependents;");
}
__device__ __forceinline__ void pdl_wait() {
    asm volatile("griddepcontrol.wait;" ::: "memory");
}

__device__ __forceinline__ float et_of(float x) {
    // exp(leaky_relu(x, 0.01)) ; leaky_relu(x) == max(x, 0.01x)
    float lr = fmaxf(x, 0.01f * x);
    return __expf(lr);
}

__global__ void zero_rowsum_kernel() {
    pdl_trigger();
    int i = blockIdx.x * blockDim.x + threadIdx.x;
    if (i < N_NODES / 4) {
        reinterpret_cast<float4*>(g_rowsum)[i] = make_float4(0.f, 0.f, 0.f, 0.f);
    }
}

__global__ void accum_kernel(const int* __restrict__ row,
                             const float* __restrict__ attr,
                             int E) {
    pdl_trigger();
    long long i = (long long)(blockIdx.x * blockDim.x + threadIdx.x) * 4;
    if (i + 3 < E) {
        // independent streaming loads issue BEFORE waiting on zero_rowsum
        int4   r = *reinterpret_cast<const int4*>(row + i);
        float4 a = *reinterpret_cast<const float4*>(attr + i);
        float e0 = et_of(a.x), e1 = et_of(a.y), e2 = et_of(a.z), e3 = et_of(a.w);
        pdl_wait();
        atomicAdd(&g_rowsum[r.x], e0);
        atomicAdd(&g_rowsum[r.y], e1);
        atomicAdd(&g_rowsum[r.z], e2);
        atomicAdd(&g_rowsum[r.w], e3);
    } else {
        pdl_wait();
        for (; i < E; i++) {
            atomicAdd(&g_rowsum[row[i]], et_of(attr[i]));
        }
    }
}

__global__ void norm_kernel(const int* __restrict__ row,
                            const float* __restrict__ attr,
                            float* __restrict__ out,
                            int E) {
    long long i = (long long)(blockIdx.x * blockDim.x + threadIdx.x) * 4;
    if (i + 3 < E) {
        // streaming prologue overlaps accum_kernel's tail via PDL
        int4   r = *reinterpret_cast<const int4*>(row + i);
        float4 a = *reinterpret_cast<const float4*>(attr + i);
        float e0 = et_of(a.x), e1 = et_of(a.y), e2 = et_of(a.z), e3 = et_of(a.w);
        pdl_wait();
        float s0 = __ldg(&g_rowsum[r.x]);
        float s1 = __ldg(&g_rowsum[r.y]);
        float s2 = __ldg(&g_rowsum[r.z]);
        float s3 = __ldg(&g_rowsum[r.w]);
        float4 o;
        o.x = __fdividef(e0, s0);
        o.y = __fdividef(e1, s1);
        o.z = __fdividef(e2, s2);
        o.w = __fdividef(e3, s3);
        // L2-only store: keep L1 wavefront/tag capacity for the gathers
        __stcg(reinterpret_cast<float4*>(out + i), o);
    } else {
        pdl_wait();
        for (; i < E; i++) {
            out[i] = __fdividef(et_of(attr[i]), __ldg(&g_rowsum[row[i]]));
        }
    }
}

extern "C" void kernel_launch(void* const* d_in, const int* in_sizes, int n_in,
                              void* d_out, int out_size) {
    // metadata order: edge_index (int32, [2, E] row-major), edge_attr (f32, [E]), N
    const int*   edge_index = (const int*)d_in[0];
    const float* edge_attr  = (const float*)d_in[1];
    float*       out        = (float*)d_out;

    int E = in_sizes[1];           // edge_attr element count
    const int* row = edge_index;   // edge_index[0] = first E elements

    const unsigned ZTPB = 256;
    const unsigned TPB = 128;      // smaller CTAs: finer wave balance, lower spread
    unsigned node_blocks = (N_NODES / 4 + ZTPB - 1) / ZTPB;
    unsigned edge_threads = (unsigned)((E + 3) / 4);
    unsigned edge_blocks = (edge_threads + TPB - 1) / TPB;

    cudaLaunchAttribute pdl_attr[1];
    pdl_attr[0].id = cudaLaunchAttributeProgrammaticStreamSerialization;
    pdl_attr[0].val.programmaticStreamSerializationAllowed = 1;

    // zero: first kernel, plain launch
    zero_rowsum_kernel<<<node_blocks, ZTPB>>>();

    {   // accum (PDL-dependent on zero)
        cudaLaunchConfig_t cfg = {};
        cfg.gridDim = dim3(edge_blocks);
        cfg.blockDim = dim3(TPB);
        cfg.attrs = pdl_attr;
        cfg.numAttrs = 1;
        cudaLaunchKernelEx(&cfg, accum_kernel, row, edge_attr, E);
    }
    {   // norm (PDL-dependent on accum)
        cudaLaunchConfig_t cfg = {};
        cfg.gridDim = dim3(edge_blocks);
        cfg.blockDim = dim3(TPB);
        cfg.attrs = pdl_attr;
        cfg.numAttrs = 1;
        cudaLaunchKernelEx(&cfg, norm_kernel, row, edge_attr, out, E);
    }
}